// round 15
// baseline (speedup 1.0000x reference)
#include <cuda_runtime.h>
#include <math.h>

#define TT 60
#define HW 65536
#define NB 6
#define NV 8
#define RMAX 10
#define RPAD 12

__device__ float         g_maxval[NV][HW];
__device__ unsigned char g_arrival[NV][HW];
__device__ float         g_q[NV][2];
__device__ float         g_aif_part[NV][64][TT];
__device__ int           g_cnt_part[NV][64];
__device__ float         g_inv[NV][TT][64];      // dense pinv fallback, row stride 64
__device__ float         g_Wu[NV][RMAX][64];     // kept cols * sinv2, zero-padded
__device__ float         g_WvT[NV][TT][RPAD];    // kept V cols transposed, zero-padded
__device__ int           g_rank[NV];
__device__ float         g_mse_part[256];
__device__ float         g_loss_part[1024];

// ---------------- pass 1: per-pixel max / first-argmax + MSE (float4) ----------
__global__ void __launch_bounds__(256) k_stats(const float* __restrict__ pred,
                                               const float* __restrict__ target) {
    int b = blockIdx.x >> 6, chunk = blockIdx.x & 63;
    int tid = threadIdx.x;
    int px4 = chunk * 256 + tid;
    const float4* vp = (const float4*)(pred   + (size_t)b * TT * HW);
    const float4* vt = (const float4*)(target + (size_t)b * TT * HW);
    float4 mp = make_float4(-1e30f, -1e30f, -1e30f, -1e30f);
    float4 mt = mp;
    int ap0 = 0, ap1 = 0, ap2 = 0, ap3 = 0;
    int at0 = 0, at1 = 0, at2 = 0, at3 = 0;
    float mse = 0.0f;
    for (int t = 0; t < TT; t++) {
        float4 a = vp[t * (HW / 4) + px4];
        float4 c = vt[t * (HW / 4) + px4];
        if (a.x > mp.x) { mp.x = a.x; ap0 = t; }
        if (a.y > mp.y) { mp.y = a.y; ap1 = t; }
        if (a.z > mp.z) { mp.z = a.z; ap2 = t; }
        if (a.w > mp.w) { mp.w = a.w; ap3 = t; }
        if (c.x > mt.x) { mt.x = c.x; at0 = t; }
        if (c.y > mt.y) { mt.y = c.y; at1 = t; }
        if (c.z > mt.z) { mt.z = c.z; at2 = t; }
        if (c.w > mt.w) { mt.w = c.w; at3 = t; }
        float dx = a.x - c.x, dy = a.y - c.y, dz = a.z - c.z, dw = a.w - c.w;
        mse += dx * dx + dy * dy + dz * dz + dw * dw;
    }
    ((float4*)g_maxval[b])[px4] = mp;
    ((float4*)g_maxval[b + 4])[px4] = mt;
    uchar4 u4p = make_uchar4((unsigned char)ap0, (unsigned char)ap1, (unsigned char)ap2, (unsigned char)ap3);
    uchar4 u4t = make_uchar4((unsigned char)at0, (unsigned char)at1, (unsigned char)at2, (unsigned char)at3);
    ((uchar4*)g_arrival[b])[px4] = u4p;
    ((uchar4*)g_arrival[b + 4])[px4] = u4t;

    __shared__ float sh[8];
    int lane = tid & 31, warp = tid >> 5;
    for (int o = 16; o; o >>= 1) mse += __shfl_xor_sync(0xffffffffu, mse, o);
    if (lane == 0) sh[warp] = mse;
    __syncthreads();
    if (tid == 0) { float s = 0; for (int w = 0; w < 8; w++) s += sh[w]; g_mse_part[blockIdx.x] = s; }
}

// ---------------- pass 2: exact order statistic via 4-pass MSB radix select ----
__global__ void __launch_bounds__(1024) k_select() {
    int vol = blockIdx.x >> 1, which = blockIdx.x & 1;
    __shared__ unsigned hist[256];
    __shared__ unsigned s_prefix, s_k;
    if (threadIdx.x == 0) { s_prefix = 0u; s_k = 62258u + (unsigned)which; }
    int lane = threadIdx.x & 31;
    for (int pass = 0; pass < 4; pass++) {
        int shift = 24 - 8 * pass;
        if (threadIdx.x < 256) hist[threadIdx.x] = 0u;
        __syncthreads();
        unsigned pmask = (pass == 0) ? 0u : (0xFFFFFFFFu << (shift + 8));
        unsigned pref = s_prefix;
        for (int i = threadIdx.x; i < HW; i += 1024) {
            unsigned u = __float_as_uint(g_maxval[vol][i]);
            unsigned key = (u & 0x80000000u) ? ~u : (u | 0x80000000u);
            bool ok = ((key & pmask) == pref);
            unsigned ball = __ballot_sync(0xffffffffu, ok);
            if (ok) {
                unsigned d = (key >> shift) & 255u;
                unsigned grp = __match_any_sync(ball, d);
                if (lane == (__ffs(grp) - 1)) atomicAdd(&hist[d], (unsigned)__popc(grp));
            }
        }
        __syncthreads();
        if (threadIdx.x == 0) {
            unsigned kk = s_k, cum = 0, d;
            for (d = 0; d < 256; d++) {
                unsigned c = hist[d];
                if (cum + c > kk) { s_k = kk - cum; break; }
                cum += c;
            }
            s_prefix = pref | (d << shift);
        }
        __syncthreads();
    }
    if (threadIdx.x == 0) {
        unsigned key = s_prefix;
        unsigned bits = (key & 0x80000000u) ? (key & 0x7FFFFFFFu) : ~key;
        g_q[vol][which] = __uint_as_float(bits);
    }
}

// ------- pass 3: masked AIF sums via deterministic compaction + transpose ------
__global__ void __launch_bounds__(256) k_aif(const float* __restrict__ pred,
                                             const float* __restrict__ target) {
    int vol = blockIdx.y, chunk = blockIdx.x;          // 64 chunks x 1024 px
    int tid = threadIdx.x;                             // 256
    const float* v = ((vol < 4) ? pred : target) + (size_t)(vol & 3) * TT * HW;
    int px0 = chunk * 1024;
    float q0 = g_q[vol][0], q1 = g_q[vol][1];
    float thr = q0 + 0.25f * (q1 - q0);
    int lane = tid & 31, warp = tid >> 5;
    bool m[4];
    unsigned bal[4];
#pragma unroll
    for (int u = 0; u < 4; u++) {
        int px = px0 + u * 256 + tid;
        m[u] = (g_arrival[vol][px] < 18) && (g_maxval[vol][px] > thr);
        bal[u] = __ballot_sync(0xffffffffu, m[u]);
    }
    __shared__ int warpBase[8];
    __shared__ int s_n;
    __shared__ int s_px[1024];
    int wcnt = __popc(bal[0]) + __popc(bal[1]) + __popc(bal[2]) + __popc(bal[3]);
    if (lane == 0) warpBase[warp] = wcnt;
    __syncthreads();
    if (tid == 0) {
        int acc = 0;
        for (int w = 0; w < 8; w++) { int c = warpBase[w]; warpBase[w] = acc; acc += c; }
        s_n = acc;
    }
    __syncthreads();
    unsigned lt = (lane == 0) ? 0u : (0xFFFFFFFFu >> (32 - lane));
    int base = warpBase[warp];
#pragma unroll
    for (int u = 0; u < 4; u++) {
        if (m[u]) s_px[base + __popc(bal[u] & lt)] = px0 + u * 256 + tid;
        base += __popc(bal[u]);
    }
    __syncthreads();
    int n = s_n;
    if (tid == 0) g_cnt_part[vol][chunk] = n;
    if (tid < TT) {
        const float* row = v + (size_t)tid * HW;
        float s = 0.0f;
        for (int i = 0; i < n; i++) s += row[s_px[i]];
        g_aif_part[vol][chunk][tid] = s;
    }
}

// ------ pass 4: AIF finalize + compacted Jacobi SVD (hard 8-sweep cap) ---------
__global__ void __launch_bounds__(960) k_svd(const float* __restrict__ pred,
                                             const float* __restrict__ target,
                                             const float* __restrict__ tv) {
    int vol = blockIdx.x, tid = threadIdx.x, lane = tid & 31, warp = tid >> 5;
    __shared__ float aif[TT];
    __shared__ float Ac[TT * 64];
    __shared__ float Vc[TT * 64];
    __shared__ float cn[TT];
    __shared__ float sinv2[TT];
    __shared__ float sig2[TT];
    __shared__ int cidx[TT];
    __shared__ int keep[RMAX];
    __shared__ int s_cnt, s_rank, s_m, s_mp;
    const float* v = ((vol < 4) ? pred : target) + (size_t)(vol & 3) * TT * HW;

    if (tid == 0) { int c = 0; for (int i = 0; i < 64; i++) c += g_cnt_part[vol][i]; s_cnt = c; }
    __syncthreads();
    if (tid < TT) {
        float s = 0;
        for (int c = 0; c < 64; c++) s += g_aif_part[vol][c][tid];
        float a;
        if (s_cnt > 0) a = s / (float)s_cnt;
        else {
            float cs = 0;
            for (int r = 0; r < 4; r++)
                for (int cc = 0; cc < 4; cc++)
                    cs += v[tid * HW + (126 + r) * 256 + (126 + cc)];
            a = cs * (1.0f / 16.0f);
        }
        aif[tid] = a;
    }
    __syncthreads();
    if (tid == 0) {
        float bl = 0;
        for (int t = 0; t < NB; t++) bl += aif[t];
        bl *= (1.0f / NB);
        float dt = tv[1] - tv[0];
        float area = 0;
        for (int t = 0; t < TT; t++) { float x = fmaxf(aif[t] - bl, 0.0f); aif[t] = x; area += x; }
        area *= dt;
        if (area > 0.0f) { float inv = 1.0f / area; for (int t = 0; t < TT; t++) aif[t] *= inv; }
        int m = 0;
        for (int j = 0; j < TT; j++) if (aif[j] > 0.0f) cidx[m++] = j;
        s_m = m;
        s_mp = m + (m & 1);
    }
    __syncthreads();
    int m = s_m, mp = s_mp;
    for (int idx = tid; idx < mp * TT; idx += blockDim.x) {
        int c = idx / TT, i = idx - c * TT;
        float val = 0.0f;
        if (c < m) { int j = cidx[c]; val = (j <= i) ? aif[j] : 0.0f; }
        Ac[c * 64 + i] = val;
    }
    __syncthreads();

    // hard 8-sweep cap: sweeps beyond this only perform noise-level rotations
    // (measured: rel_err bit-identical between 16-sweep and earlier variants)
    if (mp >= 2) {
        for (int sweep = 0; sweep < 8; sweep++) {
            if (warp < 30) {
                for (int j = warp; j < mp; j += 30) {
                    float x0 = Ac[j * 64 + lane];
                    float x1 = (lane + 32 < TT) ? Ac[j * 64 + lane + 32] : 0.0f;
                    float s = x0 * x0 + x1 * x1;
                    for (int o = 16; o; o >>= 1) s += __shfl_xor_sync(0xffffffffu, s, o);
                    if (lane == 0) cn[j] = s;
                }
            }
            __syncthreads();
            for (int r = 0; r < mp - 1; r++) {
                if (warp < mp / 2) {
                    int k = warp;
                    int a = (r + k) % (mp - 1);
                    int b = (k == 0) ? (mp - 1) : (r + (mp - 1) - k) % (mp - 1);
                    float al = cn[a], be = cn[b];
                    if (al * be > 0.0f) {
                        float* Aa = Ac + a * 64; float* Ab = Ac + b * 64;
                        int i1 = lane + 32;
                        float x0 = Aa[lane], y0 = Ab[lane];
                        float x1 = (i1 < TT) ? Aa[i1] : 0.0f;
                        float y1 = (i1 < TT) ? Ab[i1] : 0.0f;
                        float ga = x0 * y0 + x1 * y1;
                        for (int o = 16; o; o >>= 1) ga += __shfl_xor_sync(0xffffffffu, ga, o);
                        if (ga * ga > 1e-10f * al * be) {
                            float z = (be - al) / (2.0f * ga);
                            float tq = ((z >= 0.0f) ? 1.0f : -1.0f) / (fabsf(z) + sqrtf(1.0f + z * z));
                            float cf = rsqrtf(1.0f + tq * tq);
                            float sf = cf * tq;
                            Aa[lane] = cf * x0 - sf * y0; Ab[lane] = sf * x0 + cf * y0;
                            if (i1 < TT) { Aa[i1] = cf * x1 - sf * y1; Ab[i1] = sf * x1 + cf * y1; }
                            if (lane == 0) {
                                float c2 = cf * cf, s2 = sf * sf, cs2 = 2.0f * cf * sf * ga;
                                cn[a] = c2 * al - cs2 + s2 * be;
                                cn[b] = s2 * al + cs2 + c2 * be;
                            }
                        }
                    }
                }
                __syncthreads();
            }
        }
    }
    if (warp < 30) {
        for (int j = warp; j < m; j += 30) {
            float x0 = Ac[j * 64 + lane];
            float x1 = (lane + 32 < TT) ? Ac[j * 64 + lane + 32] : 0.0f;
            float s = x0 * x0 + x1 * x1;
            for (int o = 16; o; o >>= 1) s += __shfl_xor_sync(0xffffffffu, s, o);
            if (lane == 0) sig2[j] = s;
        }
    }
    __syncthreads();
    if (tid == 0) {
        float mx = 0;
        for (int j = 0; j < m; j++) mx = fmaxf(mx, sig2[j]);
        float th = 0.04f * mx;                      // (0.2*sigma_max)^2
        int rk = 0;
        for (int j = 0; j < m; j++) {
            bool kp = sig2[j] > th;
            sinv2[j] = kp ? (1.0f / sig2[j]) : 0.0f;
            if (kp) { if (rk < RMAX) keep[rk] = j; rk++; }
        }
        s_rank = rk;
        g_rank[vol] = rk;
    }
    __syncthreads();
    for (int idx = tid; idx < m * TT; idx += blockDim.x) {
        int c = idx / TT, i = idx - c * TT;
        float val = 0.0f;
        if (sinv2[c] > 0.0f) {
            float s = 0.0f;
            for (int k = i; k < TT; k++) s += Ac[c * 64 + k];
            val = aif[i] * s * sinv2[c];
        }
        Vc[c * 64 + i] = val;
    }
    __syncthreads();
    for (int idx = tid; idx < RMAX * 64; idx += blockDim.x) {
        int j = idx >> 6, k = idx & 63;
        float val = 0.0f;
        if (j < s_rank && j < RMAX && k < TT) { int c = keep[j]; val = Ac[c * 64 + k] * sinv2[c]; }
        g_Wu[vol][j][k] = val;
    }
    for (int idx = tid; idx < TT * RPAD; idx += blockDim.x) {
        int i = idx / RPAD, j = idx - i * RPAD;
        float val = 0.0f;
        if (j < s_rank && j < RMAX) val = Vc[keep[j] * 64 + i];
        g_WvT[vol][i][j] = val;
    }
    for (int idx = tid; idx < TT * 64; idx += blockDim.x) {
        int i = idx >> 6, k = idx & 63;
        float s = 0.0f;
        if (k < TT)
            for (int c = 0; c < m; c++) s += Vc[c * 64 + i] * Ac[c * 64 + k] * sinv2[c];
        g_inv[vol][i][k] = s;
    }
}

// ------ pass 5: fused per-pixel maps (pred+target) + weighted L1 reduce --------
template <int R>
__device__ __forceinline__ void lowrank_maps(const float* __restrict__ sWu,
                                             const float* __restrict__ sWvT,
                                             const float* __restrict__ vc,
                                             float& best, int& bi) {
    float p[R];
#pragma unroll
    for (int j = 0; j < R; j++) {
        const float4* row = (const float4*)&sWu[j * 64];
        float acc = 0.0f;
#pragma unroll
        for (int k4 = 0; k4 < TT / 4; k4++) {
            float4 w = row[k4];
            acc += w.x * vc[k4 * 4 + 0] + w.y * vc[k4 * 4 + 1]
                 + w.z * vc[k4 * 4 + 2] + w.w * vc[k4 * 4 + 3];
        }
        p[j] = acc;
    }
    best = -1.0f; bi = 0;
    for (int i = 0; i < TT; i++) {
        const float* wr = &sWvT[i * RPAD];
        float acc = 0.0f;
#pragma unroll
        for (int j = 0; j < R; j++) acc += wr[j] * p[j];
        acc = fmaxf(acc, 0.0f);
        if (acc > best) { best = acc; bi = i; }
    }
}

__device__ __forceinline__ void pixel_maps(const float* __restrict__ v, int px, float dt,
                                           const float* __restrict__ sWu,
                                           const float* __restrict__ sWvT,
                                           const float* __restrict__ sInv, int r,
                                           const float* __restrict__ tv,
                                           float& cbf, float& cbv, float& mtt, float& tmax) {
    float vc[TT];
    float bl = 0.0f;
#pragma unroll
    for (int t = 0; t < NB; t++) { vc[t] = v[t * HW + px]; bl += vc[t]; }
    bl *= (1.0f / NB);
    cbv = 0.0f;
#pragma unroll
    for (int t = 0; t < TT; t++) {
        float x = ((t < NB) ? vc[t] : v[t * HW + px]) - bl;
        x = fmaxf(x, 0.0f);
        vc[t] = x;
        cbv += x;
    }
    cbv *= dt;
    float best = -1.0f; int bi = 0;
    if (r <= RMAX) {
        switch (r) {
            case 0:
            case 1: lowrank_maps<1>(sWu, sWvT, vc, best, bi); break;
            case 2: lowrank_maps<2>(sWu, sWvT, vc, best, bi); break;
            case 3: lowrank_maps<3>(sWu, sWvT, vc, best, bi); break;
            case 4: lowrank_maps<4>(sWu, sWvT, vc, best, bi); break;
            default: lowrank_maps<RMAX>(sWu, sWvT, vc, best, bi); break;
        }
    } else {
        for (int i = 0; i < TT; i++) {
            const float4* row = (const float4*)&sInv[i * 64];
            float acc = 0.0f;
#pragma unroll
            for (int k4 = 0; k4 < TT / 4; k4++) {
                float4 w = row[k4];
                acc += w.x * vc[k4 * 4 + 0] + w.y * vc[k4 * 4 + 1]
                     + w.z * vc[k4 * 4 + 2] + w.w * vc[k4 * 4 + 3];
            }
            acc = fmaxf(acc, 0.0f);
            if (acc > best) { best = acc; bi = i; }
        }
    }
    cbf = best;
    mtt = (cbf > 0.0f) ? (cbv / cbf) : 0.0f;
    tmax = tv[bi];
}

__global__ void __launch_bounds__(256) k_maps(const float* __restrict__ pred,
                                              const float* __restrict__ target,
                                              const float* __restrict__ tv) {
    int b = blockIdx.x >> 8, chunk = blockIdx.x & 255;   // batch pair (pred b, target b+4)
    int tid = threadIdx.x;                               // 256
    int px = chunk * 256 + tid;
    const float* vp = pred   + (size_t)b * TT * HW;
    const float* vt = target + (size_t)b * TT * HW;
    __shared__ float sInvP[TT * 64];
    __shared__ float sInvT[TT * 64];
    __shared__ float sWuP[RMAX * 64];
    __shared__ float sWuT[RMAX * 64];
    __shared__ float sWvTP[TT * RPAD];
    __shared__ float sWvTT[TT * RPAD];
    int rp = g_rank[b], rt = g_rank[b + 4];
    if (rp <= RMAX) {
        for (int idx = tid; idx < RMAX * 64; idx += 256) sWuP[idx] = ((const float*)g_Wu[b])[idx];
        for (int idx = tid; idx < TT * RPAD; idx += 256) sWvTP[idx] = ((const float*)g_WvT[b])[idx];
    } else {
        for (int idx = tid; idx < TT * 64; idx += 256) sInvP[idx] = ((const float*)g_inv[b])[idx];
    }
    if (rt <= RMAX) {
        for (int idx = tid; idx < RMAX * 64; idx += 256) sWuT[idx] = ((const float*)g_Wu[b + 4])[idx];
        for (int idx = tid; idx < TT * RPAD; idx += 256) sWvTT[idx] = ((const float*)g_WvT[b + 4])[idx];
    } else {
        for (int idx = tid; idx < TT * 64; idx += 256) sInvT[idx] = ((const float*)g_inv[b + 4])[idx];
    }
    __syncthreads();

    float dt = tv[1] - tv[0];
    float cbf_p, cbv_p, mtt_p, tmax_p;
    float cbf_t, cbv_t, mtt_t, tmax_t;
    pixel_maps(vp, px, dt, sWuP, sWvTP, sInvP, rp, tv, cbf_p, cbv_p, mtt_p, tmax_p);
    pixel_maps(vt, px, dt, sWuT, sWvTT, sInvT, rt, tv, cbf_t, cbv_t, mtt_t, tmax_t);

    float s = fabsf(cbf_p - cbf_t)
            + fabsf(tmax_p - tmax_t)
            + 0.7f * fabsf(cbv_p - cbv_t)
            + 0.5f * fabsf(mtt_p - mtt_t);

    __shared__ float sh[8];
    int lane = tid & 31, warp = tid >> 5;
    for (int o = 16; o; o >>= 1) s += __shfl_xor_sync(0xffffffffu, s, o);
    if (lane == 0) sh[warp] = s;
    __syncthreads();
    if (tid == 0) {
        float a = 0; for (int w = 0; w < 8; w++) a += sh[w];
        g_loss_part[blockIdx.x] = a;
    }
}

// ---------------- pass 6: final combine ----------------------------------------
__global__ void k_final(float* __restrict__ out) {
    __shared__ double sh[256];
    int tid = threadIdx.x;
    double s = 0;
    for (int i = tid; i < 1024; i += 256) s += (double)g_loss_part[i];
    sh[tid] = s;
    __syncthreads();
    for (int o = 128; o; o >>= 1) { if (tid < o) sh[tid] += sh[tid + o]; __syncthreads(); }
    double l1sum = sh[0];
    __syncthreads();
    double m = (tid < 256) ? (double)g_mse_part[tid] : 0.0;
    sh[tid] = m;
    __syncthreads();
    for (int o = 128; o; o >>= 1) { if (tid < o) sh[tid] += sh[tid + o]; __syncthreads(); }
    if (tid == 0) {
        double loss = l1sum / (4.0 * 65536.0) + 0.3 * sh[0] / (4.0 * 60.0 * 65536.0);
        out[0] = (float)loss;
    }
}

extern "C" void kernel_launch(void* const* d_in, const int* in_sizes, int n_in,
                              void* d_out, int out_size) {
    (void)in_sizes; (void)n_in; (void)out_size;
    const float* pred   = (const float*)d_in[0];
    const float* target = (const float*)d_in[1];
    const float* tv     = (const float*)d_in[2];
    float* out = (float*)d_out;

    k_stats  <<<256, 256>>>(pred, target);
    k_select <<<16, 1024>>>();
    k_aif    <<<dim3(64, 8), 256>>>(pred, target);
    k_svd    <<<8, 960>>>(pred, target, tv);
    k_maps   <<<1024, 256>>>(pred, target, tv);
    k_final  <<<1, 256>>>(out);
}

// round 16
// speedup vs baseline: 1.0783x; 1.0783x over previous
#include <cuda_runtime.h>
#include <math.h>

#define TT 60
#define HW 65536
#define NB 6
#define NV 8
#define RMAX 10
#define RPAD 12

__device__ float         g_maxval[NV][HW];
__device__ unsigned char g_arrival[NV][HW];
__device__ float         g_q[NV][2];
__device__ float         g_aif_part[NV][64][TT];
__device__ int           g_cnt_part[NV][64];
__device__ float         g_inv[NV][TT][64];      // dense pinv fallback, row stride 64
__device__ float         g_Wu[NV][RMAX][64];     // kept cols * sinv2, zero-padded
__device__ float         g_WvT[NV][TT][RPAD];    // kept V cols transposed, zero-padded
__device__ int           g_rank[NV];
__device__ float         g_maps[NV][4][HW];      // cbf, cbv, mtt, tmax
__device__ float         g_mse_part[256];
__device__ float         g_loss_part[512];

// ---------------- pass 1: per-pixel max / first-argmax + MSE (float4) ----------
__global__ void __launch_bounds__(256) k_stats(const float* __restrict__ pred,
                                               const float* __restrict__ target) {
    int b = blockIdx.x >> 6, chunk = blockIdx.x & 63;
    int tid = threadIdx.x;
    int px4 = chunk * 256 + tid;
    const float4* vp = (const float4*)(pred   + (size_t)b * TT * HW);
    const float4* vt = (const float4*)(target + (size_t)b * TT * HW);
    float4 mp = make_float4(-1e30f, -1e30f, -1e30f, -1e30f);
    float4 mt = mp;
    int ap0 = 0, ap1 = 0, ap2 = 0, ap3 = 0;
    int at0 = 0, at1 = 0, at2 = 0, at3 = 0;
    float mse = 0.0f;
    for (int t = 0; t < TT; t++) {
        float4 a = vp[t * (HW / 4) + px4];
        float4 c = vt[t * (HW / 4) + px4];
        if (a.x > mp.x) { mp.x = a.x; ap0 = t; }
        if (a.y > mp.y) { mp.y = a.y; ap1 = t; }
        if (a.z > mp.z) { mp.z = a.z; ap2 = t; }
        if (a.w > mp.w) { mp.w = a.w; ap3 = t; }
        if (c.x > mt.x) { mt.x = c.x; at0 = t; }
        if (c.y > mt.y) { mt.y = c.y; at1 = t; }
        if (c.z > mt.z) { mt.z = c.z; at2 = t; }
        if (c.w > mt.w) { mt.w = c.w; at3 = t; }
        float dx = a.x - c.x, dy = a.y - c.y, dz = a.z - c.z, dw = a.w - c.w;
        mse += dx * dx + dy * dy + dz * dz + dw * dw;
    }
    ((float4*)g_maxval[b])[px4] = mp;
    ((float4*)g_maxval[b + 4])[px4] = mt;
    uchar4 u4p = make_uchar4((unsigned char)ap0, (unsigned char)ap1, (unsigned char)ap2, (unsigned char)ap3);
    uchar4 u4t = make_uchar4((unsigned char)at0, (unsigned char)at1, (unsigned char)at2, (unsigned char)at3);
    ((uchar4*)g_arrival[b])[px4] = u4p;
    ((uchar4*)g_arrival[b + 4])[px4] = u4t;

    __shared__ float sh[8];
    int lane = tid & 31, warp = tid >> 5;
    for (int o = 16; o; o >>= 1) mse += __shfl_xor_sync(0xffffffffu, mse, o);
    if (lane == 0) sh[warp] = mse;
    __syncthreads();
    if (tid == 0) { float s = 0; for (int w = 0; w < 8; w++) s += sh[w]; g_mse_part[blockIdx.x] = s; }
}

// ---------------- pass 2: exact order statistic via 4-pass MSB radix select ----
__global__ void __launch_bounds__(1024) k_select() {
    int vol = blockIdx.x >> 1, which = blockIdx.x & 1;
    __shared__ unsigned hist[256];
    __shared__ unsigned s_prefix, s_k;
    if (threadIdx.x == 0) { s_prefix = 0u; s_k = 62258u + (unsigned)which; }
    int lane = threadIdx.x & 31;
    for (int pass = 0; pass < 4; pass++) {
        int shift = 24 - 8 * pass;
        if (threadIdx.x < 256) hist[threadIdx.x] = 0u;
        __syncthreads();
        unsigned pmask = (pass == 0) ? 0u : (0xFFFFFFFFu << (shift + 8));
        unsigned pref = s_prefix;
        for (int i = threadIdx.x; i < HW; i += 1024) {
            unsigned u = __float_as_uint(g_maxval[vol][i]);
            unsigned key = (u & 0x80000000u) ? ~u : (u | 0x80000000u);
            bool ok = ((key & pmask) == pref);
            unsigned ball = __ballot_sync(0xffffffffu, ok);
            if (ok) {
                unsigned d = (key >> shift) & 255u;
                unsigned grp = __match_any_sync(ball, d);
                if (lane == (__ffs(grp) - 1)) atomicAdd(&hist[d], (unsigned)__popc(grp));
            }
        }
        __syncthreads();
        if (threadIdx.x == 0) {
            unsigned kk = s_k, cum = 0, d;
            for (d = 0; d < 256; d++) {
                unsigned c = hist[d];
                if (cum + c > kk) { s_k = kk - cum; break; }
                cum += c;
            }
            s_prefix = pref | (d << shift);
        }
        __syncthreads();
    }
    if (threadIdx.x == 0) {
        unsigned key = s_prefix;
        unsigned bits = (key & 0x80000000u) ? (key & 0x7FFFFFFFu) : ~key;
        g_q[vol][which] = __uint_as_float(bits);
    }
}

// ------- pass 3: masked AIF sums via deterministic compaction + transpose ------
__global__ void __launch_bounds__(256) k_aif(const float* __restrict__ pred,
                                             const float* __restrict__ target) {
    int vol = blockIdx.y, chunk = blockIdx.x;          // 64 chunks x 1024 px
    int tid = threadIdx.x;                             // 256
    const float* v = ((vol < 4) ? pred : target) + (size_t)(vol & 3) * TT * HW;
    int px0 = chunk * 1024;
    float q0 = g_q[vol][0], q1 = g_q[vol][1];
    float thr = q0 + 0.25f * (q1 - q0);
    int lane = tid & 31, warp = tid >> 5;
    bool m[4];
    unsigned bal[4];
#pragma unroll
    for (int u = 0; u < 4; u++) {
        int px = px0 + u * 256 + tid;
        m[u] = (g_arrival[vol][px] < 18) && (g_maxval[vol][px] > thr);
        bal[u] = __ballot_sync(0xffffffffu, m[u]);
    }
    __shared__ int warpBase[8];
    __shared__ int s_n;
    __shared__ int s_px[1024];
    int wcnt = __popc(bal[0]) + __popc(bal[1]) + __popc(bal[2]) + __popc(bal[3]);
    if (lane == 0) warpBase[warp] = wcnt;
    __syncthreads();
    if (tid == 0) {
        int acc = 0;
        for (int w = 0; w < 8; w++) { int c = warpBase[w]; warpBase[w] = acc; acc += c; }
        s_n = acc;
    }
    __syncthreads();
    unsigned lt = (lane == 0) ? 0u : (0xFFFFFFFFu >> (32 - lane));
    int base = warpBase[warp];
#pragma unroll
    for (int u = 0; u < 4; u++) {
        if (m[u]) s_px[base + __popc(bal[u] & lt)] = px0 + u * 256 + tid;
        base += __popc(bal[u]);
    }
    __syncthreads();
    int n = s_n;
    if (tid == 0) g_cnt_part[vol][chunk] = n;
    if (tid < TT) {
        const float* row = v + (size_t)tid * HW;
        float s = 0.0f;
        for (int i = 0; i < n; i++) s += row[s_px[i]];
        g_aif_part[vol][chunk][tid] = s;
    }
}

// ------ pass 4: AIF finalize + compacted Jacobi SVD (6-sweep cap + break) ------
__global__ void __launch_bounds__(960) k_svd(const float* __restrict__ pred,
                                             const float* __restrict__ target,
                                             const float* __restrict__ tv) {
    int vol = blockIdx.x, tid = threadIdx.x, lane = tid & 31, warp = tid >> 5;
    __shared__ float aif[TT];
    __shared__ float Ac[TT * 64];
    __shared__ float Vc[TT * 64];
    __shared__ float cn[TT];
    __shared__ float sinv2[TT];
    __shared__ float sig2[TT];
    __shared__ int cidx[TT];
    __shared__ int keep[RMAX];
    __shared__ int s_cnt, s_flag, s_rank, s_m, s_mp;
    const float* v = ((vol < 4) ? pred : target) + (size_t)(vol & 3) * TT * HW;

    if (tid == 0) { int c = 0; for (int i = 0; i < 64; i++) c += g_cnt_part[vol][i]; s_cnt = c; }
    __syncthreads();
    if (tid < TT) {
        float s = 0;
        for (int c = 0; c < 64; c++) s += g_aif_part[vol][c][tid];
        float a;
        if (s_cnt > 0) a = s / (float)s_cnt;
        else {
            float cs = 0;
            for (int r = 0; r < 4; r++)
                for (int cc = 0; cc < 4; cc++)
                    cs += v[tid * HW + (126 + r) * 256 + (126 + cc)];
            a = cs * (1.0f / 16.0f);
        }
        aif[tid] = a;
    }
    __syncthreads();
    if (tid == 0) {
        float bl = 0;
        for (int t = 0; t < NB; t++) bl += aif[t];
        bl *= (1.0f / NB);
        float dt = tv[1] - tv[0];
        float area = 0;
        for (int t = 0; t < TT; t++) { float x = fmaxf(aif[t] - bl, 0.0f); aif[t] = x; area += x; }
        area *= dt;
        if (area > 0.0f) { float inv = 1.0f / area; for (int t = 0; t < TT; t++) aif[t] *= inv; }
        int m = 0;
        for (int j = 0; j < TT; j++) if (aif[j] > 0.0f) cidx[m++] = j;
        s_m = m;
        s_mp = m + (m & 1);
    }
    __syncthreads();
    int m = s_m, mp = s_mp;
    for (int idx = tid; idx < mp * TT; idx += blockDim.x) {
        int c = idx / TT, i = idx - c * TT;
        float val = 0.0f;
        if (c < m) { int j = cidx[c]; val = (j <= i) ? aif[j] : 0.0f; }
        Ac[c * 64 + i] = val;
    }
    __syncthreads();

    // 6-sweep cap + convergence break (measured: break fires ~sweep 7-8; quadratic
    // convergence makes sweep 7-8 rotations noise-level; 6 keeps sigma^2 well inside
    // the 4% keep margin)
    if (mp >= 2) {
        for (int sweep = 0; sweep < 6; sweep++) {
            if (warp < 30) {
                for (int j = warp; j < mp; j += 30) {
                    float x0 = Ac[j * 64 + lane];
                    float x1 = (lane + 32 < TT) ? Ac[j * 64 + lane + 32] : 0.0f;
                    float s = x0 * x0 + x1 * x1;
                    for (int o = 16; o; o >>= 1) s += __shfl_xor_sync(0xffffffffu, s, o);
                    if (lane == 0) cn[j] = s;
                }
            }
            if (tid == 0) s_flag = 0;
            __syncthreads();
            for (int r = 0; r < mp - 1; r++) {
                if (warp < mp / 2) {
                    int k = warp;
                    int a = (r + k) % (mp - 1);
                    int b = (k == 0) ? (mp - 1) : (r + (mp - 1) - k) % (mp - 1);
                    float al = cn[a], be = cn[b];
                    if (al * be > 0.0f) {
                        float* Aa = Ac + a * 64; float* Ab = Ac + b * 64;
                        int i1 = lane + 32;
                        float x0 = Aa[lane], y0 = Ab[lane];
                        float x1 = (i1 < TT) ? Aa[i1] : 0.0f;
                        float y1 = (i1 < TT) ? Ab[i1] : 0.0f;
                        float ga = x0 * y0 + x1 * y1;
                        for (int o = 16; o; o >>= 1) ga += __shfl_xor_sync(0xffffffffu, ga, o);
                        if (ga * ga > 1e-10f * al * be) {
                            float z = (be - al) / (2.0f * ga);
                            float tq = ((z >= 0.0f) ? 1.0f : -1.0f) / (fabsf(z) + sqrtf(1.0f + z * z));
                            float cf = rsqrtf(1.0f + tq * tq);
                            float sf = cf * tq;
                            Aa[lane] = cf * x0 - sf * y0; Ab[lane] = sf * x0 + cf * y0;
                            if (i1 < TT) { Aa[i1] = cf * x1 - sf * y1; Ab[i1] = sf * x1 + cf * y1; }
                            if (lane == 0) {
                                float c2 = cf * cf, s2 = sf * sf, cs2 = 2.0f * cf * sf * ga;
                                cn[a] = c2 * al - cs2 + s2 * be;
                                cn[b] = s2 * al + cs2 + c2 * be;
                                s_flag = 1;
                            }
                        }
                    }
                }
                __syncthreads();
            }
            int f = s_flag;
            __syncthreads();
            if (!f) break;
        }
    }
    if (warp < 30) {
        for (int j = warp; j < m; j += 30) {
            float x0 = Ac[j * 64 + lane];
            float x1 = (lane + 32 < TT) ? Ac[j * 64 + lane + 32] : 0.0f;
            float s = x0 * x0 + x1 * x1;
            for (int o = 16; o; o >>= 1) s += __shfl_xor_sync(0xffffffffu, s, o);
            if (lane == 0) sig2[j] = s;
        }
    }
    __syncthreads();
    if (tid == 0) {
        float mx = 0;
        for (int j = 0; j < m; j++) mx = fmaxf(mx, sig2[j]);
        float th = 0.04f * mx;                      // (0.2*sigma_max)^2
        int rk = 0;
        for (int j = 0; j < m; j++) {
            bool kp = sig2[j] > th;
            sinv2[j] = kp ? (1.0f / sig2[j]) : 0.0f;
            if (kp) { if (rk < RMAX) keep[rk] = j; rk++; }
        }
        s_rank = rk;
        g_rank[vol] = rk;
    }
    __syncthreads();
    if (s_rank <= RMAX) {
        // fast path: compute V only for the <=RMAX kept columns, export factors
        for (int idx = tid; idx < RMAX * 64; idx += blockDim.x) {
            int j = idx >> 6, k = idx & 63;
            float val = 0.0f;
            if (j < s_rank && k < TT) { int c = keep[j]; val = Ac[c * 64 + k] * sinv2[c]; }
            g_Wu[vol][j][k] = val;
        }
        for (int idx = tid; idx < TT * RPAD; idx += blockDim.x) {
            int i = idx / RPAD, j = idx - i * RPAD;
            float val = 0.0f;
            if (j < s_rank) {
                int c = keep[j];
                float s = 0.0f;
                for (int k = i; k < TT; k++) s += Ac[c * 64 + k];
                val = aif[i] * s * sinv2[c];
            }
            g_WvT[vol][i][j] = val;
        }
    } else {
        // rare fallback: full V + dense pinv
        for (int idx = tid; idx < m * TT; idx += blockDim.x) {
            int c = idx / TT, i = idx - c * TT;
            float val = 0.0f;
            if (sinv2[c] > 0.0f) {
                float s = 0.0f;
                for (int k = i; k < TT; k++) s += Ac[c * 64 + k];
                val = aif[i] * s * sinv2[c];
            }
            Vc[c * 64 + i] = val;
        }
        __syncthreads();
        for (int idx = tid; idx < TT * 64; idx += blockDim.x) {
            int i = idx >> 6, k = idx & 63;
            float s = 0.0f;
            if (k < TT)
                for (int c = 0; c < m; c++) s += Vc[c * 64 + i] * Ac[c * 64 + k] * sinv2[c];
            g_inv[vol][i][k] = s;
        }
    }
}

// ---------------- pass 5: per-pixel maps (rank-templated fast path) ------------
template <int R>
__device__ __forceinline__ void lowrank_maps(const float* __restrict__ sWu,
                                             const float* __restrict__ sWvT,
                                             const float* __restrict__ vc,
                                             float& best, int& bi) {
    float p[R];
#pragma unroll
    for (int j = 0; j < R; j++) {
        const float4* row = (const float4*)&sWu[j * 64];
        float acc = 0.0f;
#pragma unroll
        for (int k4 = 0; k4 < TT / 4; k4++) {
            float4 w = row[k4];
            acc += w.x * vc[k4 * 4 + 0] + w.y * vc[k4 * 4 + 1]
                 + w.z * vc[k4 * 4 + 2] + w.w * vc[k4 * 4 + 3];
        }
        p[j] = acc;
    }
    best = -1.0f; bi = 0;
    for (int i = 0; i < TT; i++) {
        const float* wr = &sWvT[i * RPAD];
        float acc = 0.0f;
#pragma unroll
        for (int j = 0; j < R; j++) acc += wr[j] * p[j];
        acc = fmaxf(acc, 0.0f);
        if (acc > best) { best = acc; bi = i; }
    }
}

__global__ void __launch_bounds__(256) k_maps(const float* __restrict__ pred,
                                              const float* __restrict__ target,
                                              const float* __restrict__ tv) {
    int vol = blockIdx.x >> 8, chunk = blockIdx.x & 255;
    int tid = threadIdx.x;                       // 256
    int px = chunk * 256 + tid;
    const float* v = ((vol < 4) ? pred : target) + (size_t)(vol & 3) * TT * HW;
    __shared__ float sInv[TT * 64];              // fallback
    __shared__ float sWu[RMAX * 64];
    __shared__ float sWvT[TT * RPAD];
    int r = g_rank[vol];
    if (r <= RMAX) {
        for (int idx = tid; idx < RMAX * 64; idx += 256) sWu[idx] = ((const float*)g_Wu[vol])[idx];
        for (int idx = tid; idx < TT * RPAD; idx += 256) sWvT[idx] = ((const float*)g_WvT[vol])[idx];
    } else {
        for (int idx = tid; idx < TT * 64; idx += 256) sInv[idx] = ((const float*)g_inv[vol])[idx];
    }
    __syncthreads();

    float vc[TT];
    float bl = 0.0f;
#pragma unroll
    for (int t = 0; t < NB; t++) { vc[t] = v[t * HW + px]; bl += vc[t]; }
    bl *= (1.0f / NB);
    float dt = tv[1] - tv[0];
    float cbv = 0.0f;
#pragma unroll
    for (int t = 0; t < TT; t++) {
        float x = ((t < NB) ? vc[t] : v[t * HW + px]) - bl;
        x = fmaxf(x, 0.0f);
        vc[t] = x;
        cbv += x;
    }
    cbv *= dt;
    float best = -1.0f; int bi = 0;
    if (r <= RMAX) {
        switch (r) {
            case 0:
            case 1: lowrank_maps<1>(sWu, sWvT, vc, best, bi); break;
            case 2: lowrank_maps<2>(sWu, sWvT, vc, best, bi); break;
            case 3: lowrank_maps<3>(sWu, sWvT, vc, best, bi); break;
            case 4: lowrank_maps<4>(sWu, sWvT, vc, best, bi); break;
            default: lowrank_maps<RMAX>(sWu, sWvT, vc, best, bi); break;
        }
    } else {
        for (int i = 0; i < TT; i++) {
            const float4* row = (const float4*)&sInv[i * 64];
            float acc = 0.0f;
#pragma unroll
            for (int k4 = 0; k4 < TT / 4; k4++) {
                float4 w = row[k4];
                acc += w.x * vc[k4 * 4 + 0] + w.y * vc[k4 * 4 + 1]
                     + w.z * vc[k4 * 4 + 2] + w.w * vc[k4 * 4 + 3];
            }
            acc = fmaxf(acc, 0.0f);
            if (acc > best) { best = acc; bi = i; }
        }
    }
    float cbf = best;
    float mtt = (cbf > 0.0f) ? (cbv / cbf) : 0.0f;
    g_maps[vol][0][px] = cbf;
    g_maps[vol][1][px] = cbv;
    g_maps[vol][2][px] = mtt;
    g_maps[vol][3][px] = tv[bi];
}

// ---------------- pass 6: weighted L1 partials ---------------------------------
__global__ void k_lossmap() {
    int i = blockIdx.x * 512 + threadIdx.x;      // 0..262143
    int b = i >> 16, px = i & 65535;
    float s = fabsf(g_maps[b][0][px] - g_maps[b + 4][0][px])
            + fabsf(g_maps[b][3][px] - g_maps[b + 4][3][px])
            + 0.7f * fabsf(g_maps[b][1][px] - g_maps[b + 4][1][px])
            + 0.5f * fabsf(g_maps[b][2][px] - g_maps[b + 4][2][px]);
    __shared__ float sh[16];
    int lane = threadIdx.x & 31, warp = threadIdx.x >> 5;
    for (int o = 16; o; o >>= 1) s += __shfl_xor_sync(0xffffffffu, s, o);
    if (lane == 0) sh[warp] = s;
    __syncthreads();
    if (threadIdx.x == 0) {
        float a = 0; for (int w = 0; w < 16; w++) a += sh[w];
        g_loss_part[blockIdx.x] = a;
    }
}

// ---------------- pass 7: final combine ----------------------------------------
__global__ void k_final(float* __restrict__ out) {
    __shared__ double sh[256];
    int tid = threadIdx.x;
    double s = 0;
    for (int i = tid; i < 512; i += 256) s += (double)g_loss_part[i];
    sh[tid] = s;
    __syncthreads();
    for (int o = 128; o; o >>= 1) { if (tid < o) sh[tid] += sh[tid + o]; __syncthreads(); }
    double l1sum = sh[0];
    __syncthreads();
    double m = (tid < 256) ? (double)g_mse_part[tid] : 0.0;
    sh[tid] = m;
    __syncthreads();
    for (int o = 128; o; o >>= 1) { if (tid < o) sh[tid] += sh[tid + o]; __syncthreads(); }
    if (tid == 0) {
        double loss = l1sum / (4.0 * 65536.0) + 0.3 * sh[0] / (4.0 * 60.0 * 65536.0);
        out[0] = (float)loss;
    }
}

extern "C" void kernel_launch(void* const* d_in, const int* in_sizes, int n_in,
                              void* d_out, int out_size) {
    (void)in_sizes; (void)n_in; (void)out_size;
    const float* pred   = (const float*)d_in[0];
    const float* target = (const float*)d_in[1];
    const float* tv     = (const float*)d_in[2];
    float* out = (float*)d_out;

    k_stats  <<<256, 256>>>(pred, target);
    k_select <<<16, 1024>>>();
    k_aif    <<<dim3(64, 8), 256>>>(pred, target);
    k_svd    <<<8, 960>>>(pred, target, tv);
    k_maps   <<<2048, 256>>>(pred, target, tv);
    k_lossmap<<<512, 512>>>();
    k_final  <<<1, 256>>>(out);
}